// round 15
// baseline (speedup 1.0000x reference)
#include <cuda_runtime.h>

// 2-layer LSTM (B=1024, T=512, I=1, H=64) + FC(64->1).
// 128 CTAs x 8 batches, 256 threads/CTA (2 warps/SMSP), SMEM-resident.
// Gate-pair packing: accumulators are {gate g0, gate g0+1} per batch, so
// weight pairs load as natural LDS.64 (no duplication MOVs) and the hidden
// state is stored DUPLICATED in SMEM so LDS.128 yields {h_b,h_b} operands.
// Two barriers per timestep: fused matvec (gates1(t) + gates0(t+1)) then
// fused elementwise update (h1(t) + h0(t+1)).

typedef unsigned long long u64;

#define NB    8
#define NCTA  128
#define NTHR  256
#define TLEN  512

// SMEM float layout
#define W0_OFF   0                       // W0T [64][256]   = 16384
#define W1_OFF   16384                   // W1T [128][256]  = 32768
#define XB_OFF   (16384 + 32768)         // xb_dup [128][8][2] = 2048
#define GB_OFF   (XB_OFF + 2048)         // gb [2][8][256]  = 4096
#define V_OFF    (GB_OFF + 4096)         // v_dup [128][20] = 2560 (16 data + 4 pad)
#define SMEM_FLOATS (V_OFF + 2560)
#define SMEM_BYTES  (SMEM_FLOATS * 4)

__device__ __forceinline__ u64 pk2(float a, float b) {
    u64 r; asm("mov.b64 %0,{%1,%2};" : "=l"(r) : "f"(a), "f"(b)); return r;
}
__device__ __forceinline__ void fma2(u64 &d, u64 a, u64 b) {
    asm("fma.rn.f32x2 %0,%1,%2,%0;" : "+l"(d) : "l"(a), "l"(b));
}
__device__ __forceinline__ u64 lds64(unsigned a) {
    u64 r; asm volatile("ld.shared.b64 %0,[%1];" : "=l"(r) : "r"(a)); return r;
}
__device__ __forceinline__ void lds128(u64 &a, u64 &b, unsigned addr) {
    asm volatile("ld.shared.v2.u64 {%0,%1},[%2];" : "=l"(a), "=l"(b) : "r"(addr));
}
__device__ __forceinline__ void sts64(unsigned addr, u64 a) {
    asm volatile("st.shared.b64 [%0],%1;" :: "r"(addr), "l"(a) : "memory");
}

__device__ __forceinline__ float sigm(float x) {
    return __fdividef(1.0f, 1.0f + __expf(-x));
}
__device__ __forceinline__ float tanh_(float x) {
    x = fminf(15.0f, fmaxf(-15.0f, x));
    float e = __expf(-2.0f * x);
    return __fdividef(1.0f - e, 1.0f + e);
}

__global__ void __launch_bounds__(NTHR, 1)
lstm2_kernel(const float* __restrict__ x,
             const float* __restrict__ Wih0, const float* __restrict__ Whh0,
             const float* __restrict__ bih0, const float* __restrict__ bhh0,
             const float* __restrict__ Wih1, const float* __restrict__ Whh1,
             const float* __restrict__ bih1, const float* __restrict__ bhh1,
             const float* __restrict__ Wfc,  const float* __restrict__ bfc,
             float* __restrict__ out)
{
    extern __shared__ float sm[];
    float* W0T = sm + W0_OFF;     // [k][gate]  (transposed Whh0)
    float* W1T = sm + W1_OFF;     // [k][gate]  (rows 0..63 Wih1, 64..127 Whh1, transposed)
    float* xb  = sm + XB_OFF;     // [tloc][b][2]  duplicated x chunk (128 steps)
    float* gb  = sm + GB_OFF;     // [layer][b][gate]
    float* v   = sm + V_OFF;      // [k][b][2] + pad  duplicated hidden state

    const int tid = threadIdx.x;
    const int b0  = blockIdx.x * NB;

    // ---- stage weights, transposed: row k, gates contiguous ----
    for (int i = tid; i < 256 * 64; i += NTHR) {
        int j = i >> 6, k = i & 63;              // gate row j, hidden col k
        W0T[k * 256 + j]        = Whh0[i];
        W1T[k * 256 + j]        = Wih1[i];
        W1T[(k + 64) * 256 + j] = Whh1[i];
    }
    // ---- zero hidden state (incl. pad) ----
    for (int i = tid; i < 128 * 20; i += NTHR) v[i] = 0.0f;
    // ---- x chunk 0 (t in [0,128)), duplicated ----
    for (int i = tid; i < 1024; i += NTHR) {
        int bb = i >> 7, tl = i & 127;
        float xv = x[(size_t)(b0 + bb) * TLEN + tl];
        xb[tl * 16 + bb * 2]     = xv;
        xb[tl * 16 + bb * 2 + 1] = xv;
    }

    // ---- matvec-role constants: thread owns gate pair (g0,g0+1) x 4 batches ----
    const int gp = tid & 127, g0 = 2 * gp, bh = tid >> 7;
    const u64 bi0 = pk2(bih0[g0] + bhh0[g0], bih0[g0 + 1] + bhh0[g0 + 1]);
    const u64 bi1 = pk2(bih1[g0] + bhh1[g0], bih1[g0 + 1] + bhh1[g0 + 1]);
    const u64 wx  = pk2(Wih0[g0], Wih0[g0 + 1]);

    const unsigned sbase = (unsigned)__cvta_generic_to_shared(sm);
    const unsigned w0p  = sbase + (W0_OFF + g0) * 4;            // + k*1024
    const unsigned w1p  = sbase + (W1_OFF + g0) * 4;            // + k*1024
    const unsigned xbp  = sbase + XB_OFF * 4 + bh * 32;         // + tloc*64
    const unsigned vp   = sbase + V_OFF * 4 + bh * 32;          // + k*80
    const unsigned gst0 = sbase + GB_OFF * 4 + bh * 4096 + g0 * 4;  // + j*1024
    const unsigned gst1 = gst0 + 2048 * 4;

    // ---- update-role constants: thread owns (layer ul, unit uu, 4 batches) ----
    const int ul = tid >> 7, uu = tid & 63, ubg = (tid >> 6) & 1;
    const float* gbu = gb + ul * 2048 + ubg * 1024 + uu;        // + q*256 (+64j per gate)
    const unsigned vwp = sbase + (V_OFF + (ul * 64 + uu) * 20 + ubg * 8) * 4;  // + q*8
    float creg[4] = {0.f, 0.f, 0.f, 0.f};

    __syncthreads();

    // ===== prologue: gates0(0) = bias + wx*x(0)  (h0(-1)=0, no matvec) =====
    {
        u64 xd0, xd1, xd2, xd3;
        lds128(xd0, xd1, xbp); lds128(xd2, xd3, xbp + 16);
        u64 a0 = bi0, a1 = bi0, a2 = bi0, a3 = bi0;
        fma2(a0, wx, xd0); fma2(a1, wx, xd1); fma2(a2, wx, xd2); fma2(a3, wx, xd3);
        sts64(gst0, a0); sts64(gst0 + 1024, a1);
        sts64(gst0 + 2048, a2); sts64(gst0 + 3072, a3);
    }
    __syncthreads();
    if (ul == 0) {                       // layer-0 update for t=0 -> h0(0)
        #pragma unroll
        for (int q = 0; q < 4; q++) {
            float iv = gbu[q * 256], fv = gbu[q * 256 + 64];
            float gv = gbu[q * 256 + 128], ov = gbu[q * 256 + 192];
            float c = __fmaf_rn(sigm(fv), creg[q], sigm(iv) * tanh_(gv));
            creg[q] = c;
            float h = sigm(ov) * tanh_(c);
            sts64(vwp + q * 8, pk2(h, h));
        }
    }
    __syncthreads();

    // ===== main loop: iteration t computes gates1(t) & gates0(t+1), then
    //       updates h1(t) & h0(t+1). =====
    for (int t = 0; t < TLEN; t++) {
        // refill x chunk when crossing a 128-step boundary (not at the very end)
        if ((t & 127) == 127 && t != TLEN - 1) {
            for (int i = tid; i < 1024; i += NTHR) {
                int bb = i >> 7, tl = i & 127;
                float xv = x[(size_t)(b0 + bb) * TLEN + (t + 1) + tl];
                xb[tl * 16 + bb * 2]     = xv;
                xb[tl * 16 + bb * 2 + 1] = xv;
            }
            __syncthreads();
        }

        // ---- fused matvec ----
        u64 a10 = bi1, a11 = bi1, a12 = bi1, a13 = bi1;
        u64 a00 = bi0, a01 = bi0, a02 = bi0, a03 = bi0;
        {
            unsigned xp = xbp + (unsigned)((t + 1) & 127) * 64;
            u64 xd0, xd1, xd2, xd3;
            lds128(xd0, xd1, xp); lds128(xd2, xd3, xp + 16);
            fma2(a00, wx, xd0); fma2(a01, wx, xd1);
            fma2(a02, wx, xd2); fma2(a03, wx, xd3);
        }
        #pragma unroll 8
        for (int k = 0; k < 64; k++) {          // shared h0(t) rows: both layers
            u64 w1 = lds64(w1p + (unsigned)k * 1024);
            u64 w0 = lds64(w0p + (unsigned)k * 1024);
            u64 h0, h1, h2, h3;
            lds128(h0, h1, vp + (unsigned)k * 80);
            lds128(h2, h3, vp + (unsigned)k * 80 + 16);
            fma2(a10, w1, h0); fma2(a11, w1, h1); fma2(a12, w1, h2); fma2(a13, w1, h3);
            fma2(a00, w0, h0); fma2(a01, w0, h1); fma2(a02, w0, h2); fma2(a03, w0, h3);
        }
        #pragma unroll 8
        for (int k = 64; k < 128; k++) {        // h1(t-1) rows: layer-1 only
            u64 w1 = lds64(w1p + (unsigned)k * 1024);
            u64 h0, h1, h2, h3;
            lds128(h0, h1, vp + (unsigned)k * 80);
            lds128(h2, h3, vp + (unsigned)k * 80 + 16);
            fma2(a10, w1, h0); fma2(a11, w1, h1); fma2(a12, w1, h2); fma2(a13, w1, h3);
        }
        sts64(gst1, a10); sts64(gst1 + 1024, a11);
        sts64(gst1 + 2048, a12); sts64(gst1 + 3072, a13);
        sts64(gst0, a00); sts64(gst0 + 1024, a01);
        sts64(gst0 + 2048, a02); sts64(gst0 + 3072, a03);
        __syncthreads();

        // ---- fused update: layer-1 (t) and layer-0 (t+1) ----
        #pragma unroll
        for (int q = 0; q < 4; q++) {
            float iv = gbu[q * 256], fv = gbu[q * 256 + 64];
            float gv = gbu[q * 256 + 128], ov = gbu[q * 256 + 192];
            float c = __fmaf_rn(sigm(fv), creg[q], sigm(iv) * tanh_(gv));
            creg[q] = c;
            float h = sigm(ov) * tanh_(c);
            sts64(vwp + q * 8, pk2(h, h));
        }
        __syncthreads();
    }

    // ===== FC: out[b] = h1(511) . Wfc + bfc =====
    if (tid < NB) {
        float s = bfc[0];
        #pragma unroll 16
        for (int u = 0; u < 64; u++)
            s = __fmaf_rn(Wfc[u], v[(64 + u) * 20 + tid * 2], s);
        out[b0 + tid] = s;
    }
}

extern "C" void kernel_launch(void* const* d_in, const int* in_sizes, int n_in,
                              void* d_out, int out_size) {
    (void)in_sizes; (void)n_in; (void)out_size;
    const float* x    = (const float*)d_in[0];
    const float* Wih0 = (const float*)d_in[1];
    const float* Whh0 = (const float*)d_in[2];
    const float* bih0 = (const float*)d_in[3];
    const float* bhh0 = (const float*)d_in[4];
    const float* Wih1 = (const float*)d_in[5];
    const float* Whh1 = (const float*)d_in[6];
    const float* bih1 = (const float*)d_in[7];
    const float* bhh1 = (const float*)d_in[8];
    const float* Wfc  = (const float*)d_in[9];
    const float* bfc  = (const float*)d_in[10];
    float* out = (float*)d_out;

    cudaFuncSetAttribute(lstm2_kernel,
                         cudaFuncAttributeMaxDynamicSharedMemorySize, SMEM_BYTES);
    lstm2_kernel<<<NCTA, NTHR, SMEM_BYTES>>>(x, Wih0, Whh0, bih0, bhh0,
                                             Wih1, Whh1, bih1, bhh1,
                                             Wfc, bfc, out);
}

// round 16
// speedup vs baseline: 1.0007x; 1.0007x over previous
#include <cuda_runtime.h>

// 2-layer LSTM (B=1024, T=512, I=1, H=64) + FC(64->1).
// 128 CTAs x 8 batches, 256 threads/CTA (2 warps/SMSP), SMEM-resident.
// Gate-pair packing: accumulators are {gate g0, gate g0+1} per batch, so
// weight pairs load as natural LDS.64 (no duplication MOVs) and the hidden
// state is stored DUPLICATED in SMEM so LDS.128 yields {h_b,h_b} operands.
// Two barriers per timestep: fused matvec (gates1(t) + gates0(t+1)) then
// fused elementwise update (h1(t) + h0(t+1)).

typedef unsigned long long u64;

#define NB    8
#define NCTA  128
#define NTHR  256
#define TLEN  512

// SMEM float layout
#define W0_OFF   0                       // W0T [64][256]   = 16384
#define W1_OFF   16384                   // W1T [128][256]  = 32768
#define XB_OFF   (16384 + 32768)         // xb_dup [128][8][2] = 2048
#define GB_OFF   (XB_OFF + 2048)         // gb [2][8][256]  = 4096
#define V_OFF    (GB_OFF + 4096)         // v_dup [128][20] = 2560 (16 data + 4 pad)
#define SMEM_FLOATS (V_OFF + 2560)
#define SMEM_BYTES  (SMEM_FLOATS * 4)

__device__ __forceinline__ u64 pk2(float a, float b) {
    u64 r; asm("mov.b64 %0,{%1,%2};" : "=l"(r) : "f"(a), "f"(b)); return r;
}
__device__ __forceinline__ void fma2(u64 &d, u64 a, u64 b) {
    asm("fma.rn.f32x2 %0,%1,%2,%0;" : "+l"(d) : "l"(a), "l"(b));
}
__device__ __forceinline__ u64 lds64(unsigned a) {
    u64 r; asm volatile("ld.shared.b64 %0,[%1];" : "=l"(r) : "r"(a)); return r;
}
__device__ __forceinline__ void lds128(u64 &a, u64 &b, unsigned addr) {
    asm volatile("ld.shared.v2.u64 {%0,%1},[%2];" : "=l"(a), "=l"(b) : "r"(addr));
}
__device__ __forceinline__ void sts64(unsigned addr, u64 a) {
    asm volatile("st.shared.b64 [%0],%1;" :: "r"(addr), "l"(a) : "memory");
}

__device__ __forceinline__ float sigm(float x) {
    return __fdividef(1.0f, 1.0f + __expf(-x));
}
__device__ __forceinline__ float tanh_(float x) {
    x = fminf(15.0f, fmaxf(-15.0f, x));
    float e = __expf(-2.0f * x);
    return __fdividef(1.0f - e, 1.0f + e);
}

__global__ void __launch_bounds__(NTHR, 1)
lstm2_kernel(const float* __restrict__ x,
             const float* __restrict__ Wih0, const float* __restrict__ Whh0,
             const float* __restrict__ bih0, const float* __restrict__ bhh0,
             const float* __restrict__ Wih1, const float* __restrict__ Whh1,
             const float* __restrict__ bih1, const float* __restrict__ bhh1,
             const float* __restrict__ Wfc,  const float* __restrict__ bfc,
             float* __restrict__ out)
{
    extern __shared__ float sm[];
    float* W0T = sm + W0_OFF;     // [k][gate]  (transposed Whh0)
    float* W1T = sm + W1_OFF;     // [k][gate]  (rows 0..63 Wih1, 64..127 Whh1, transposed)
    float* xb  = sm + XB_OFF;     // [tloc][b][2]  duplicated x chunk (128 steps)
    float* gb  = sm + GB_OFF;     // [layer][b][gate]
    float* v   = sm + V_OFF;      // [k][b][2] + pad  duplicated hidden state

    const int tid = threadIdx.x;
    const int b0  = blockIdx.x * NB;

    // ---- stage weights, transposed: row k, gates contiguous ----
    for (int i = tid; i < 256 * 64; i += NTHR) {
        int j = i >> 6, k = i & 63;              // gate row j, hidden col k
        W0T[k * 256 + j]        = Whh0[i];
        W1T[k * 256 + j]        = Wih1[i];
        W1T[(k + 64) * 256 + j] = Whh1[i];
    }
    // ---- zero hidden state (incl. pad) ----
    for (int i = tid; i < 128 * 20; i += NTHR) v[i] = 0.0f;
    // ---- x chunk 0 (t in [0,128)), duplicated ----
    for (int i = tid; i < 1024; i += NTHR) {
        int bb = i >> 7, tl = i & 127;
        float xv = x[(size_t)(b0 + bb) * TLEN + tl];
        xb[tl * 16 + bb * 2]     = xv;
        xb[tl * 16 + bb * 2 + 1] = xv;
    }

    // ---- matvec-role constants: thread owns gate pair (g0,g0+1) x 4 batches ----
    const int gp = tid & 127, g0 = 2 * gp, bh = tid >> 7;
    const u64 bi0 = pk2(bih0[g0] + bhh0[g0], bih0[g0 + 1] + bhh0[g0 + 1]);
    const u64 bi1 = pk2(bih1[g0] + bhh1[g0], bih1[g0 + 1] + bhh1[g0 + 1]);
    const u64 wx  = pk2(Wih0[g0], Wih0[g0 + 1]);

    const unsigned sbase = (unsigned)__cvta_generic_to_shared(sm);
    const unsigned w0p  = sbase + (W0_OFF + g0) * 4;            // + k*1024
    const unsigned w1p  = sbase + (W1_OFF + g0) * 4;            // + k*1024
    const unsigned xbp  = sbase + XB_OFF * 4 + bh * 32;         // + tloc*64
    const unsigned vp   = sbase + V_OFF * 4 + bh * 32;          // + k*80
    const unsigned gst0 = sbase + GB_OFF * 4 + bh * 4096 + g0 * 4;  // + j*1024
    const unsigned gst1 = gst0 + 2048 * 4;

    // ---- update-role constants: thread owns (layer ul, unit uu, 4 batches) ----
    const int ul = tid >> 7, uu = tid & 63, ubg = (tid >> 6) & 1;
    const float* gbu = gb + ul * 2048 + ubg * 1024 + uu;        // + q*256 (+64j per gate)
    const unsigned vwp = sbase + (V_OFF + (ul * 64 + uu) * 20 + ubg * 8) * 4;  // + q*8
    float creg[4] = {0.f, 0.f, 0.f, 0.f};

    __syncthreads();

    // ===== prologue: gates0(0) = bias + wx*x(0)  (h0(-1)=0, no matvec) =====
    {
        u64 xd0, xd1, xd2, xd3;
        lds128(xd0, xd1, xbp); lds128(xd2, xd3, xbp + 16);
        u64 a0 = bi0, a1 = bi0, a2 = bi0, a3 = bi0;
        fma2(a0, wx, xd0); fma2(a1, wx, xd1); fma2(a2, wx, xd2); fma2(a3, wx, xd3);
        sts64(gst0, a0); sts64(gst0 + 1024, a1);
        sts64(gst0 + 2048, a2); sts64(gst0 + 3072, a3);
    }
    __syncthreads();
    if (ul == 0) {                       // layer-0 update for t=0 -> h0(0)
        #pragma unroll
        for (int q = 0; q < 4; q++) {
            float iv = gbu[q * 256], fv = gbu[q * 256 + 64];
            float gv = gbu[q * 256 + 128], ov = gbu[q * 256 + 192];
            float c = __fmaf_rn(sigm(fv), creg[q], sigm(iv) * tanh_(gv));
            creg[q] = c;
            float h = sigm(ov) * tanh_(c);
            sts64(vwp + q * 8, pk2(h, h));
        }
    }
    __syncthreads();

    // ===== main loop: iteration t computes gates1(t) & gates0(t+1), then
    //       updates h1(t) & h0(t+1). =====
    for (int t = 0; t < TLEN; t++) {
        // refill x chunk when crossing a 128-step boundary (not at the very end)
        if ((t & 127) == 127 && t != TLEN - 1) {
            for (int i = tid; i < 1024; i += NTHR) {
                int bb = i >> 7, tl = i & 127;
                float xv = x[(size_t)(b0 + bb) * TLEN + (t + 1) + tl];
                xb[tl * 16 + bb * 2]     = xv;
                xb[tl * 16 + bb * 2 + 1] = xv;
            }
            __syncthreads();
        }

        // ---- fused matvec ----
        u64 a10 = bi1, a11 = bi1, a12 = bi1, a13 = bi1;
        u64 a00 = bi0, a01 = bi0, a02 = bi0, a03 = bi0;
        {
            unsigned xp = xbp + (unsigned)((t + 1) & 127) * 64;
            u64 xd0, xd1, xd2, xd3;
            lds128(xd0, xd1, xp); lds128(xd2, xd3, xp + 16);
            fma2(a00, wx, xd0); fma2(a01, wx, xd1);
            fma2(a02, wx, xd2); fma2(a03, wx, xd3);
        }
        #pragma unroll 8
        for (int k = 0; k < 64; k++) {          // shared h0(t) rows: both layers
            u64 w1 = lds64(w1p + (unsigned)k * 1024);
            u64 w0 = lds64(w0p + (unsigned)k * 1024);
            u64 h0, h1, h2, h3;
            lds128(h0, h1, vp + (unsigned)k * 80);
            lds128(h2, h3, vp + (unsigned)k * 80 + 16);
            fma2(a10, w1, h0); fma2(a11, w1, h1); fma2(a12, w1, h2); fma2(a13, w1, h3);
            fma2(a00, w0, h0); fma2(a01, w0, h1); fma2(a02, w0, h2); fma2(a03, w0, h3);
        }
        #pragma unroll 8
        for (int k = 64; k < 128; k++) {        // h1(t-1) rows: layer-1 only
            u64 w1 = lds64(w1p + (unsigned)k * 1024);
            u64 h0, h1, h2, h3;
            lds128(h0, h1, vp + (unsigned)k * 80);
            lds128(h2, h3, vp + (unsigned)k * 80 + 16);
            fma2(a10, w1, h0); fma2(a11, w1, h1); fma2(a12, w1, h2); fma2(a13, w1, h3);
        }
        sts64(gst1, a10); sts64(gst1 + 1024, a11);
        sts64(gst1 + 2048, a12); sts64(gst1 + 3072, a13);
        sts64(gst0, a00); sts64(gst0 + 1024, a01);
        sts64(gst0 + 2048, a02); sts64(gst0 + 3072, a03);
        __syncthreads();

        // ---- fused update: layer-1 (t) and layer-0 (t+1) ----
        #pragma unroll
        for (int q = 0; q < 4; q++) {
            float iv = gbu[q * 256], fv = gbu[q * 256 + 64];
            float gv = gbu[q * 256 + 128], ov = gbu[q * 256 + 192];
            float c = __fmaf_rn(sigm(fv), creg[q], sigm(iv) * tanh_(gv));
            creg[q] = c;
            float h = sigm(ov) * tanh_(c);
            sts64(vwp + q * 8, pk2(h, h));
        }
        __syncthreads();
    }

    // ===== FC: out[b] = h1(511) . Wfc + bfc =====
    if (tid < NB) {
        float s = bfc[0];
        #pragma unroll 16
        for (int u = 0; u < 64; u++)
            s = __fmaf_rn(Wfc[u], v[(64 + u) * 20 + tid * 2], s);
        out[b0 + tid] = s;
    }
}

extern "C" void kernel_launch(void* const* d_in, const int* in_sizes, int n_in,
                              void* d_out, int out_size) {
    (void)in_sizes; (void)n_in; (void)out_size;
    const float* x    = (const float*)d_in[0];
    const float* Wih0 = (const float*)d_in[1];
    const float* Whh0 = (const float*)d_in[2];
    const float* bih0 = (const float*)d_in[3];
    const float* bhh0 = (const float*)d_in[4];
    const float* Wih1 = (const float*)d_in[5];
    const float* Whh1 = (const float*)d_in[6];
    const float* bih1 = (const float*)d_in[7];
    const float* bhh1 = (const float*)d_in[8];
    const float* Wfc  = (const float*)d_in[9];
    const float* bfc  = (const float*)d_in[10];
    float* out = (float*)d_out;

    cudaFuncSetAttribute(lstm2_kernel,
                         cudaFuncAttributeMaxDynamicSharedMemorySize, SMEM_BYTES);
    lstm2_kernel<<<NCTA, NTHR, SMEM_BYTES>>>(x, Wih0, Whh0, bih0, bhh0,
                                             Wih1, Whh1, bih1, bhh1,
                                             Wfc, bfc, out);
}